// round 8
// baseline (speedup 1.0000x reference)
#include <cuda_runtime.h>
#include <cuda_bf16.h>
#include <cstdint>
#include <math.h>

#define N_TOK 2048
#define D_DIM 768
#define HY 768
#define H_HEADS 12

// Scratch (allocation-free rule: device globals)
__device__ __nv_bfloat16 g_gr[N_TOK * D_DIM];   // bf16-rounded g
__device__ __nv_bfloat16 g_wqr[HY * D_DIM];     // bf16-rounded Wq
__device__ __nv_bfloat16 g_wkr[HY * D_DIM];     // bf16-rounded Wk
__device__ __nv_bfloat16 g_Q[N_TOK * HY];       // bf16, scaled by beta*log2e
__device__ __nv_bfloat16 g_K[N_TOK * HY];       // bf16
__device__ float g_partial[H_HEADS * 16];       // 192 per-block LSE2 sums
__device__ int   g_count;                       // last-block counter (self-resetting)

// ---------------------------------------------------------------------------
__device__ __forceinline__ uint32_t smem_u32(const void* p) {
    uint32_t a;
    asm("{ .reg .u64 t; cvta.to.shared.u64 t, %1; cvt.u32.u64 %0, t; }"
        : "=r"(a) : "l"(p));
    return a;
}
__device__ __forceinline__ uint32_t pack_bf2(float x, float y) {
    __nv_bfloat162 h = __floats2bfloat162_rn(x, y);
    return *reinterpret_cast<uint32_t*>(&h);
}
__device__ __forceinline__ void ldmx4(uint32_t r[4], uint32_t addr) {
    asm volatile("ldmatrix.sync.aligned.m8n8.x4.shared.b16 {%0,%1,%2,%3}, [%4];"
                 : "=r"(r[0]), "=r"(r[1]), "=r"(r[2]), "=r"(r[3]) : "r"(addr));
}
__device__ __forceinline__ void mma_bf16(float c[4], const uint32_t a[4],
                                         uint32_t b0, uint32_t b1) {
    asm volatile(
        "mma.sync.aligned.m16n8k16.row.col.f32.bf16.bf16.f32 "
        "{%0,%1,%2,%3}, {%4,%5,%6,%7}, {%8,%9}, {%0,%1,%2,%3};"
        : "+f"(c[0]), "+f"(c[1]), "+f"(c[2]), "+f"(c[3])
        : "r"(a[0]), "r"(a[1]), "r"(a[2]), "r"(a[3]), "r"(b0), "r"(b1));
}
#define CP_ASYNC16(dst, src) \
    asm volatile("cp.async.cg.shared.global [%0], [%1], 16;" :: "r"(dst), "l"(src))
#define CP_COMMIT() asm volatile("cp.async.commit_group;" ::: "memory")
#define CP_WAIT1()  asm volatile("cp.async.wait_group 1;" ::: "memory")

// ---------------------------------------------------------------------------
// Pre-round all inputs to bf16.
// ---------------------------------------------------------------------------
__global__ __launch_bounds__(256) void round_inputs(const float* __restrict__ g,
                                                    const float* __restrict__ wq,
                                                    const float* __restrict__ wk) {
    const int stride = gridDim.x * blockDim.x;
    const int i0 = blockIdx.x * blockDim.x + threadIdx.x;
    const int NG = N_TOK * D_DIM / 4, NW = HY * D_DIM / 4;
    const float4* g4  = (const float4*)g;
    const float4* wq4 = (const float4*)wq;
    const float4* wk4 = (const float4*)wk;
    uint2* og = (uint2*)g_gr;
    uint2* oq = (uint2*)g_wqr;
    uint2* ok = (uint2*)g_wkr;
    for (int t = i0; t < NG; t += stride) {
        float4 v = g4[t];
        og[t] = make_uint2(pack_bf2(v.x, v.y), pack_bf2(v.z, v.w));
    }
    for (int t = i0; t < NW; t += stride) {
        float4 v = wq4[t];
        oq[t] = make_uint2(pack_bf2(v.x, v.y), pack_bf2(v.z, v.w));
        float4 w = wk4[t];
        ok[t] = make_uint2(pack_bf2(w.x, w.y), pack_bf2(w.z, w.w));
    }
}

// ---------------------------------------------------------------------------
// Projection: Out[n][j] = sum_d G[n][d]*W[j][d].  z=0: Wq->g_Q (*beta*log2e).
// Tile 128x64, k-stage 64 bf16, 12 stages, 128 threads (2x2 warps, warp 64x32),
// cp.async 2-stage pipeline.
// Dynamic smem 48KB: As[2] @0/16K (16KB each), Bs[2] @32K/40K (8KB each).
// ---------------------------------------------------------------------------
__global__ __launch_bounds__(128) void proj_tc() {
    extern __shared__ uint32_t smd[];
    const uint32_t sb = smem_u32(smd);

    const int z = blockIdx.z;
    const __nv_bfloat16* __restrict__ W = z ? g_wkr : g_wqr;
    __nv_bfloat16* __restrict__ Out = z ? g_K : g_Q;
    const float scale = z ? 1.0f : 0.18033688011112042f;  // beta*log2(e)

    const int bm = blockIdx.y * 128, bn = blockIdx.x * 64;
    const int tid = threadIdx.x, lane = tid & 31, wid = tid >> 5;
    const int wm = wid >> 1, wn = wid & 1;
    const int lrow = tid >> 3, lg = tid & 7;   // loader: 16 rows x 8 granules(16B)

    auto issue = [&](int s, int buf) {
        const int kt = s * 64;
        const uint32_t Ab = sb + buf * 16384;
        const uint32_t Bb = sb + 32768 + buf * 8192;
#pragma unroll
        for (int i = 0; i < 8; i++) {
            int row = i * 16 + lrow;
            CP_ASYNC16(Ab + (uint32_t)(row * 8 + (lg ^ (row & 7))) * 16,
                       &g_gr[(size_t)(bm + row) * D_DIM + kt + lg * 8]);
        }
#pragma unroll
        for (int i = 0; i < 4; i++) {
            int row = i * 16 + lrow;
            CP_ASYNC16(Bb + (uint32_t)(row * 8 + (lg ^ (row & 7))) * 16,
                       &W[(size_t)(bn + row) * D_DIM + kt + lg * 8]);
        }
    };

    issue(0, 0); CP_COMMIT();
    issue(1, 1); CP_COMMIT();

    float c[4][4][4];
#pragma unroll
    for (int mf = 0; mf < 4; mf++)
#pragma unroll
        for (int nf = 0; nf < 4; nf++)
#pragma unroll
            for (int q = 0; q < 4; q++) c[mf][nf][q] = 0.f;

    const int mlo = (lane >> 3) & 1, mhi = lane >> 4, r8 = lane & 7;

    for (int s = 0; s < 12; s++) {
        CP_WAIT1();
        __syncthreads();
        const int buf = s & 1;
        const uint32_t Ab = sb + buf * 16384;
        const uint32_t Bb = sb + 32768 + buf * 8192;
#pragma unroll
        for (int ks = 0; ks < 4; ks++) {
            uint32_t a[4][4];
#pragma unroll
            for (int mf = 0; mf < 4; mf++) {
                int row = wm * 64 + mf * 16 + mlo * 8 + r8;
                int g = 2 * ks + mhi;
                ldmx4(a[mf], Ab + (uint32_t)(row * 8 + (g ^ (row & 7))) * 16);
            }
#pragma unroll
            for (int p = 0; p < 2; p++) {
                uint32_t b[4];
                int row = wn * 32 + p * 16 + mhi * 8 + r8;
                int g = 2 * ks + mlo;
                ldmx4(b, Bb + (uint32_t)(row * 8 + (g ^ (row & 7))) * 16);
#pragma unroll
                for (int mf = 0; mf < 4; mf++) {
                    mma_bf16(c[mf][2 * p],     a[mf], b[0], b[1]);
                    mma_bf16(c[mf][2 * p + 1], a[mf], b[2], b[3]);
                }
            }
        }
        __syncthreads();
        if (s + 2 < 12) issue(s + 2, buf);
        CP_COMMIT();
    }

    // store C as bf16 (attn consumes without conversion)
#pragma unroll
    for (int mf = 0; mf < 4; mf++) {
        int row = bm + wm * 64 + mf * 16 + (lane >> 2);
#pragma unroll
        for (int nf = 0; nf < 4; nf++) {
            int col = bn + wn * 32 + nf * 8 + 2 * (lane & 3);
            *(uint32_t*)&Out[(size_t)row * HY + col] =
                pack_bf2(c[mf][nf][0] * scale, c[mf][nf][1] * scale);
            *(uint32_t*)&Out[(size_t)(row + 8) * HY + col] =
                pack_bf2(c[mf][nf][2] * scale, c[mf][nf][3] * scale);
        }
    }
}

// ---------------------------------------------------------------------------
// Attention LSE: block = (128 q rows, head). 8 warps; warp w owns rows w*16..+15.
// K tiles of 128 rows (16KB bf16), cp.async 2-stage. Online log2-domain softmax
// with tile-skip (>40 log2-units below running max -> skipped).
// Halved K gmem traffic vs 64q blocks (each K tile serves 128 q rows).
// Last block performs the final 192-partial reduction and resets the counter.
// Dynamic smem 48KB: Qs @0 (16KB), Ks[2] @16K/32K (16KB each).
// ---------------------------------------------------------------------------
__global__ __launch_bounds__(256) void attn_tc(float* __restrict__ out) {
    extern __shared__ uint32_t smd[];
    const uint32_t sb = smem_u32(smd);
    __shared__ float red[128];
    __shared__ int last;

    const int h = blockIdx.y, qb = blockIdx.x, q0 = qb * 128;
    const int tid = threadIdx.x, lane = tid & 31, wid = tid >> 5;
    const int lrow = tid >> 3, lg = tid & 7;   // loader: 32 rows x 8 granules

    // issue Q (128 rows)
#pragma unroll
    for (int i = 0; i < 4; i++) {
        int row = i * 32 + lrow;
        CP_ASYNC16(sb + (uint32_t)(row * 8 + (lg ^ (row & 7))) * 16,
                   &g_Q[(size_t)(q0 + row) * HY + h * 64 + lg * 8]);
    }
    CP_COMMIT();

    auto issueK = [&](int t, int buf) {
        const uint32_t Kb = sb + 16384 + buf * 16384;
#pragma unroll
        for (int i = 0; i < 4; i++) {
            int row = i * 32 + lrow;
            CP_ASYNC16(Kb + (uint32_t)(row * 8 + (lg ^ (row & 7))) * 16,
                       &g_K[(size_t)(t * 128 + row) * HY + h * 64 + lg * 8]);
        }
    };
    issueK(0, 0); CP_COMMIT();
    issueK(1, 1); CP_COMMIT();

    CP_WAIT1();          // Q + K0 complete
    __syncthreads();

    // preload Q fragments (4 ksteps x 4 regs)
    const int mlo = (lane >> 3) & 1, mhi = lane >> 4, r8 = lane & 7;
    uint32_t QA[4][4];
#pragma unroll
    for (int ks = 0; ks < 4; ks++) {
        int row = wid * 16 + mlo * 8 + r8;
        int g = 2 * ks + mhi;
        ldmx4(QA[ks], sb + (uint32_t)(row * 8 + (g ^ (row & 7))) * 16);
    }

    float m0 = -1e30f, m1 = -1e30f, s0 = 0.f, s1 = 0.f;

    for (int t = 0; t < 16; t++) {
        if (t > 0) { CP_WAIT1(); __syncthreads(); }
        const uint32_t Kb = sb + 16384 + (t & 1) * 16384;

        float c[16][4];
#pragma unroll
        for (int nf = 0; nf < 16; nf++)
#pragma unroll
            for (int q = 0; q < 4; q++) c[nf][q] = 0.f;

#pragma unroll
        for (int ks = 0; ks < 4; ks++) {
#pragma unroll
            for (int p = 0; p < 8; p++) {
                uint32_t b[4];
                int row = p * 16 + mhi * 8 + r8;
                int g = 2 * ks + mlo;
                ldmx4(b, Kb + (uint32_t)(row * 8 + (g ^ (row & 7))) * 16);
                mma_bf16(c[2 * p],     QA[ks], b[0], b[1]);
                mma_bf16(c[2 * p + 1], QA[ks], b[2], b[3]);
            }
        }
        __syncthreads();
        if (t + 2 < 16) issueK(t + 2, t & 1);
        CP_COMMIT();

        // tile max per row group (lanes converged here)
        float lm0 = -1e30f, lm1 = -1e30f;
#pragma unroll
        for (int nf = 0; nf < 16; nf++) {
            lm0 = fmaxf(lm0, fmaxf(c[nf][0], c[nf][1]));
            lm1 = fmaxf(lm1, fmaxf(c[nf][2], c[nf][3]));
        }
        lm0 = fmaxf(lm0, __shfl_xor_sync(0xffffffffu, lm0, 1));
        lm0 = fmaxf(lm0, __shfl_xor_sync(0xffffffffu, lm0, 2));
        lm1 = fmaxf(lm1, __shfl_xor_sync(0xffffffffu, lm1, 1));
        lm1 = fmaxf(lm1, __shfl_xor_sync(0xffffffffu, lm1, 2));

        // skip tiles that cannot contribute (no shfl inside branches)
        if (lm0 >= m0 - 40.f) {
            float mn = fmaxf(m0, lm0);
            float p = 0.f;
#pragma unroll
            for (int nf = 0; nf < 16; nf++)
                p += exp2f(c[nf][0] - mn) + exp2f(c[nf][1] - mn);
            s0 = s0 * exp2f(m0 - mn) + p;   // per-lane partial sum
            m0 = mn;
        }
        if (lm1 >= m1 - 40.f) {
            float mn = fmaxf(m1, lm1);
            float p = 0.f;
#pragma unroll
            for (int nf = 0; nf < 16; nf++)
                p += exp2f(c[nf][2] - mn) + exp2f(c[nf][3] - mn);
            s1 = s1 * exp2f(m1 - mn) + p;
            m1 = mn;
        }
    }

    // reduce per-lane partials over the 4-lane row group
    s0 += __shfl_xor_sync(0xffffffffu, s0, 1);
    s0 += __shfl_xor_sync(0xffffffffu, s0, 2);
    s1 += __shfl_xor_sync(0xffffffffu, s1, 1);
    s1 += __shfl_xor_sync(0xffffffffu, s1, 2);

    if ((lane & 3) == 0) {
        red[wid * 16 + (lane >> 2)]     = m0 + log2f(s0);
        red[wid * 16 + (lane >> 2) + 8] = m1 + log2f(s1);
    }
    __syncthreads();
    if (tid < 32) {
        float v = red[tid] + red[tid + 32] + red[tid + 64] + red[tid + 96];
#pragma unroll
        for (int off = 16; off > 0; off >>= 1)
            v += __shfl_xor_sync(0xffffffffu, v, off);
        if (tid == 0) g_partial[h * 16 + qb] = v;
    }

    // --- fused final reduction: last arriving block sums all 192 partials ---
    if (tid == 0) {
        __threadfence();
        last = (atomicAdd(&g_count, 1) == H_HEADS * 16 - 1);
    }
    __syncthreads();
    if (last) {
        __threadfence();
        if (tid < 64) {
            float v = g_partial[tid] + g_partial[tid + 64] + g_partial[tid + 128];
#pragma unroll
            for (int off = 16; off > 0; off >>= 1)
                v += __shfl_xor_sync(0xffffffffu, v, off);
            if (lane == 0) red[wid] = v;
        }
        __syncthreads();
        if (tid == 0) {
            out[0] = -5.545177444479562f * (red[0] + red[1]);
            g_count = 0;   // reset for next graph replay
        }
    }
}

// ---------------------------------------------------------------------------
extern "C" void kernel_launch(void* const* d_in, const int* in_sizes, int n_in,
                              void* d_out, int out_size) {
    const float* g  = (const float*)d_in[0];
    const float* Wq = (const float*)d_in[1];
    const float* Wk = (const float*)d_in[2];
    float* out = (float*)d_out;

    cudaFuncSetAttribute(proj_tc, cudaFuncAttributeMaxDynamicSharedMemorySize, 49152);
    cudaFuncSetAttribute(attn_tc, cudaFuncAttributeMaxDynamicSharedMemorySize, 49152);

    round_inputs<<<1184, 256>>>(g, Wq, Wk);
    proj_tc<<<dim3(12, 16, 2), 128, 49152>>>();
    attn_tc<<<dim3(16, H_HEADS), 256, 49152>>>(out);
}

// round 9
// speedup vs baseline: 1.0444x; 1.0444x over previous
#include <cuda_runtime.h>
#include <cuda_bf16.h>
#include <cstdint>
#include <math.h>

#define N_TOK 2048
#define D_DIM 768
#define HY 768
#define H_HEADS 12

// Scratch (allocation-free rule: device globals)
__device__ __nv_bfloat16 g_gr[N_TOK * D_DIM];   // bf16-rounded g
__device__ __nv_bfloat16 g_wqr[HY * D_DIM];     // bf16-rounded Wq
__device__ __nv_bfloat16 g_wkr[HY * D_DIM];     // bf16-rounded Wk
__device__ __nv_bfloat16 g_Q[N_TOK * HY];       // bf16, scaled by beta*log2e
__device__ __nv_bfloat16 g_K[N_TOK * HY];       // bf16
__device__ float g_partial[H_HEADS * 32];       // 384 per-block LSE2 sums
__device__ int   g_count;                       // last-block counter (self-resetting)

// ---------------------------------------------------------------------------
__device__ __forceinline__ uint32_t smem_u32(const void* p) {
    uint32_t a;
    asm("{ .reg .u64 t; cvta.to.shared.u64 t, %1; cvt.u32.u64 %0, t; }"
        : "=r"(a) : "l"(p));
    return a;
}
__device__ __forceinline__ uint32_t pack_bf2(float x, float y) {
    __nv_bfloat162 h = __floats2bfloat162_rn(x, y);
    return *reinterpret_cast<uint32_t*>(&h);
}
__device__ __forceinline__ void ldmx4(uint32_t r[4], uint32_t addr) {
    asm volatile("ldmatrix.sync.aligned.m8n8.x4.shared.b16 {%0,%1,%2,%3}, [%4];"
                 : "=r"(r[0]), "=r"(r[1]), "=r"(r[2]), "=r"(r[3]) : "r"(addr));
}
__device__ __forceinline__ void mma_bf16(float c[4], const uint32_t a[4],
                                         uint32_t b0, uint32_t b1) {
    asm volatile(
        "mma.sync.aligned.m16n8k16.row.col.f32.bf16.bf16.f32 "
        "{%0,%1,%2,%3}, {%4,%5,%6,%7}, {%8,%9}, {%0,%1,%2,%3};"
        : "+f"(c[0]), "+f"(c[1]), "+f"(c[2]), "+f"(c[3])
        : "r"(a[0]), "r"(a[1]), "r"(a[2]), "r"(a[3]), "r"(b0), "r"(b1));
}
#define CP_ASYNC16(dst, src) \
    asm volatile("cp.async.cg.shared.global [%0], [%1], 16;" :: "r"(dst), "l"(src))
#define CP_COMMIT() asm volatile("cp.async.commit_group;" ::: "memory")
#define CP_WAIT1()  asm volatile("cp.async.wait_group 1;" ::: "memory")

// ---------------------------------------------------------------------------
// Pre-round all inputs to bf16.
// ---------------------------------------------------------------------------
__global__ __launch_bounds__(256) void round_inputs(const float* __restrict__ g,
                                                    const float* __restrict__ wq,
                                                    const float* __restrict__ wk) {
    const int stride = gridDim.x * blockDim.x;
    const int i0 = blockIdx.x * blockDim.x + threadIdx.x;
    const int NG = N_TOK * D_DIM / 4, NW = HY * D_DIM / 4;
    const float4* g4  = (const float4*)g;
    const float4* wq4 = (const float4*)wq;
    const float4* wk4 = (const float4*)wk;
    uint2* og = (uint2*)g_gr;
    uint2* oq = (uint2*)g_wqr;
    uint2* ok = (uint2*)g_wkr;
    for (int t = i0; t < NG; t += stride) {
        float4 v = g4[t];
        og[t] = make_uint2(pack_bf2(v.x, v.y), pack_bf2(v.z, v.w));
    }
    for (int t = i0; t < NW; t += stride) {
        float4 v = wq4[t];
        oq[t] = make_uint2(pack_bf2(v.x, v.y), pack_bf2(v.z, v.w));
        float4 w = wk4[t];
        ok[t] = make_uint2(pack_bf2(w.x, w.y), pack_bf2(w.z, w.w));
    }
}

// ---------------------------------------------------------------------------
// Projection: Out[n][j] = sum_d G[n][d]*W[j][d].  z=0: Wq->g_Q (*beta*log2e).
// Tile 64x64, k-stage 64 bf16, 12 stages, 128 threads (2x2 warps, warp 32x32),
// cp.async 2-stage pipeline. Grid 768 CTAs -> ~2x occupancy vs 128x64 tiles.
// Dynamic smem 32KB: As[2] @0/8K (8KB each), Bs[2] @16K/24K (8KB each).
// ---------------------------------------------------------------------------
__global__ __launch_bounds__(128, 6) void proj_tc() {
    extern __shared__ uint32_t smd[];
    const uint32_t sb = smem_u32(smd);

    const int z = blockIdx.z;
    const __nv_bfloat16* __restrict__ W = z ? g_wkr : g_wqr;
    __nv_bfloat16* __restrict__ Out = z ? g_K : g_Q;
    const float scale = z ? 1.0f : 0.18033688011112042f;  // beta*log2(e)

    const int bm = blockIdx.y * 64, bn = blockIdx.x * 64;
    const int tid = threadIdx.x, lane = tid & 31, wid = tid >> 5;
    const int wm = wid >> 1, wn = wid & 1;
    const int lrow = tid >> 3, lg = tid & 7;   // loader: 16 rows x 8 granules(16B)

    auto issue = [&](int s, int buf) {
        const int kt = s * 64;
        const uint32_t Ab = sb + buf * 8192;
        const uint32_t Bb = sb + 16384 + buf * 8192;
#pragma unroll
        for (int i = 0; i < 4; i++) {
            int row = i * 16 + lrow;
            CP_ASYNC16(Ab + (uint32_t)(row * 8 + (lg ^ (row & 7))) * 16,
                       &g_gr[(size_t)(bm + row) * D_DIM + kt + lg * 8]);
            CP_ASYNC16(Bb + (uint32_t)(row * 8 + (lg ^ (row & 7))) * 16,
                       &W[(size_t)(bn + row) * D_DIM + kt + lg * 8]);
        }
    };

    issue(0, 0); CP_COMMIT();
    issue(1, 1); CP_COMMIT();

    float c[2][4][4];
#pragma unroll
    for (int mf = 0; mf < 2; mf++)
#pragma unroll
        for (int nf = 0; nf < 4; nf++)
#pragma unroll
            for (int q = 0; q < 4; q++) c[mf][nf][q] = 0.f;

    const int mlo = (lane >> 3) & 1, mhi = lane >> 4, r8 = lane & 7;

    for (int s = 0; s < 12; s++) {
        CP_WAIT1();
        __syncthreads();
        const int buf = s & 1;
        const uint32_t Ab = sb + buf * 8192;
        const uint32_t Bb = sb + 16384 + buf * 8192;
#pragma unroll
        for (int ks = 0; ks < 4; ks++) {
            uint32_t a[2][4];
#pragma unroll
            for (int mf = 0; mf < 2; mf++) {
                int row = wm * 32 + mf * 16 + mlo * 8 + r8;
                int g = 2 * ks + mhi;
                ldmx4(a[mf], Ab + (uint32_t)(row * 8 + (g ^ (row & 7))) * 16);
            }
#pragma unroll
            for (int p = 0; p < 2; p++) {
                uint32_t b[4];
                int row = wn * 32 + p * 16 + mhi * 8 + r8;
                int g = 2 * ks + mlo;
                ldmx4(b, Bb + (uint32_t)(row * 8 + (g ^ (row & 7))) * 16);
#pragma unroll
                for (int mf = 0; mf < 2; mf++) {
                    mma_bf16(c[mf][2 * p],     a[mf], b[0], b[1]);
                    mma_bf16(c[mf][2 * p + 1], a[mf], b[2], b[3]);
                }
            }
        }
        __syncthreads();
        if (s + 2 < 12) issue(s + 2, buf);
        CP_COMMIT();
    }

    // store C as bf16 (attn consumes without conversion)
#pragma unroll
    for (int mf = 0; mf < 2; mf++) {
        int row = bm + wm * 32 + mf * 16 + (lane >> 2);
#pragma unroll
        for (int nf = 0; nf < 4; nf++) {
            int col = bn + wn * 32 + nf * 8 + 2 * (lane & 3);
            *(uint32_t*)&Out[(size_t)row * HY + col] =
                pack_bf2(c[mf][nf][0] * scale, c[mf][nf][1] * scale);
            *(uint32_t*)&Out[(size_t)(row + 8) * HY + col] =
                pack_bf2(c[mf][nf][2] * scale, c[mf][nf][3] * scale);
        }
    }
}

// ---------------------------------------------------------------------------
// Attention LSE: block = (64 q rows, head), 256 threads = 8 warps.
// Warp w: q-group qg=w>>1 (16 rows), k-half kh=w&1 (64 of the 128 k-tile rows).
// Each warp keeps its own online (m,s) per row over its k-half; exact merge of
// the two halves at the end. Tile-skip per half (>40 log2-units below max).
// Dynamic smem 40KB: Qs @0 (8KB), Ks[2] @8K/24K (16KB each).
// ---------------------------------------------------------------------------
__global__ __launch_bounds__(256, 2) void attn_tc(float* __restrict__ out) {
    extern __shared__ uint32_t smd[];
    const uint32_t sb = smem_u32(smd);
    __shared__ float redm[2][64], reds[2][64], red[64];
    __shared__ int last;

    const int h = blockIdx.y, qb = blockIdx.x, q0 = qb * 64;
    const int tid = threadIdx.x, lane = tid & 31, wid = tid >> 5;
    const int qg = wid >> 1, kh = wid & 1;
    const int lrow = tid >> 3, lg = tid & 7;   // loader: 32 rows x 8 granules

    // issue Q (64 rows)
#pragma unroll
    for (int i = 0; i < 2; i++) {
        int row = i * 32 + lrow;
        CP_ASYNC16(sb + (uint32_t)(row * 8 + (lg ^ (row & 7))) * 16,
                   &g_Q[(size_t)(q0 + row) * HY + h * 64 + lg * 8]);
    }
    CP_COMMIT();

    auto issueK = [&](int t, int buf) {
        const uint32_t Kb = sb + 8192 + buf * 16384;
#pragma unroll
        for (int i = 0; i < 4; i++) {
            int row = i * 32 + lrow;
            CP_ASYNC16(Kb + (uint32_t)(row * 8 + (lg ^ (row & 7))) * 16,
                       &g_K[(size_t)(t * 128 + row) * HY + h * 64 + lg * 8]);
        }
    };
    issueK(0, 0); CP_COMMIT();
    issueK(1, 1); CP_COMMIT();

    CP_WAIT1();          // Q + K0 complete
    __syncthreads();

    // preload Q fragments (4 ksteps x 4 regs)
    const int mlo = (lane >> 3) & 1, mhi = lane >> 4, r8 = lane & 7;
    uint32_t QA[4][4];
#pragma unroll
    for (int ks = 0; ks < 4; ks++) {
        int row = qg * 16 + mlo * 8 + r8;
        int g = 2 * ks + mhi;
        ldmx4(QA[ks], sb + (uint32_t)(row * 8 + (g ^ (row & 7))) * 16);
    }

    float m0 = -1e30f, m1 = -1e30f, s0 = 0.f, s1 = 0.f;

    for (int t = 0; t < 16; t++) {
        if (t > 0) { CP_WAIT1(); __syncthreads(); }
        const uint32_t Kb = sb + 8192 + (t & 1) * 16384;

        float c[8][4];
#pragma unroll
        for (int nf = 0; nf < 8; nf++)
#pragma unroll
            for (int q = 0; q < 4; q++) c[nf][q] = 0.f;

#pragma unroll
        for (int ks = 0; ks < 4; ks++) {
#pragma unroll
            for (int p = 0; p < 4; p++) {
                uint32_t b[4];
                int row = kh * 64 + p * 16 + mhi * 8 + r8;
                int g = 2 * ks + mlo;
                ldmx4(b, Kb + (uint32_t)(row * 8 + (g ^ (row & 7))) * 16);
                mma_bf16(c[2 * p],     QA[ks], b[0], b[1]);
                mma_bf16(c[2 * p + 1], QA[ks], b[2], b[3]);
            }
        }
        __syncthreads();
        if (t + 2 < 16) issueK(t + 2, t & 1);
        CP_COMMIT();

        // tile max per row group (lanes converged here)
        float lm0 = -1e30f, lm1 = -1e30f;
#pragma unroll
        for (int nf = 0; nf < 8; nf++) {
            lm0 = fmaxf(lm0, fmaxf(c[nf][0], c[nf][1]));
            lm1 = fmaxf(lm1, fmaxf(c[nf][2], c[nf][3]));
        }
        lm0 = fmaxf(lm0, __shfl_xor_sync(0xffffffffu, lm0, 1));
        lm0 = fmaxf(lm0, __shfl_xor_sync(0xffffffffu, lm0, 2));
        lm1 = fmaxf(lm1, __shfl_xor_sync(0xffffffffu, lm1, 1));
        lm1 = fmaxf(lm1, __shfl_xor_sync(0xffffffffu, lm1, 2));

        // skip tiles that cannot contribute (no shfl inside branches)
        if (lm0 >= m0 - 40.f) {
            float mn = fmaxf(m0, lm0);
            float p = 0.f;
#pragma unroll
            for (int nf = 0; nf < 8; nf++)
                p += exp2f(c[nf][0] - mn) + exp2f(c[nf][1] - mn);
            s0 = s0 * exp2f(m0 - mn) + p;   // per-lane partial sum
            m0 = mn;
        }
        if (lm1 >= m1 - 40.f) {
            float mn = fmaxf(m1, lm1);
            float p = 0.f;
#pragma unroll
            for (int nf = 0; nf < 8; nf++)
                p += exp2f(c[nf][2] - mn) + exp2f(c[nf][3] - mn);
            s1 = s1 * exp2f(m1 - mn) + p;
            m1 = mn;
        }
    }

    // reduce per-lane partials over the 4-lane row group
    s0 += __shfl_xor_sync(0xffffffffu, s0, 1);
    s0 += __shfl_xor_sync(0xffffffffu, s0, 2);
    s1 += __shfl_xor_sync(0xffffffffu, s1, 1);
    s1 += __shfl_xor_sync(0xffffffffu, s1, 2);

    // publish per-half (m, s) for each row
    if ((lane & 3) == 0) {
        int r = qg * 16 + (lane >> 2);
        redm[kh][r]     = m0;  reds[kh][r]     = s0;
        redm[kh][r + 8] = m1;  reds[kh][r + 8] = s1;
    }
    __syncthreads();

    // merge the two k-halves exactly; block-reduce 64 row LSEs
    if (tid < 64) {
        float ma = redm[0][tid], mb = redm[1][tid];
        float mm = fmaxf(ma, mb);
        float s = reds[0][tid] * exp2f(ma - mm) + reds[1][tid] * exp2f(mb - mm);
        float v = mm + log2f(s);
#pragma unroll
        for (int off = 16; off > 0; off >>= 1)
            v += __shfl_xor_sync(0xffffffffu, v, off);
        if (lane == 0) red[wid] = v;
    }
    __syncthreads();
    if (tid == 0) g_partial[h * 32 + qb] = red[0] + red[1];

    // --- fused final reduction: last arriving block sums all 384 partials ---
    if (tid == 0) {
        __threadfence();
        last = (atomicAdd(&g_count, 1) == H_HEADS * 32 - 1);
    }
    __syncthreads();
    if (last) {
        __threadfence();
        if (tid < 128) {
            float v = g_partial[tid] + g_partial[tid + 128] + g_partial[tid + 256];
#pragma unroll
            for (int off = 16; off > 0; off >>= 1)
                v += __shfl_xor_sync(0xffffffffu, v, off);
            if (lane == 0) red[wid] = v;
        }
        __syncthreads();
        if (tid == 0) {
            out[0] = -5.545177444479562f * (red[0] + red[1] + red[2] + red[3]);
            g_count = 0;   // reset for next graph replay
        }
    }
}

// ---------------------------------------------------------------------------
extern "C" void kernel_launch(void* const* d_in, const int* in_sizes, int n_in,
                              void* d_out, int out_size) {
    const float* g  = (const float*)d_in[0];
    const float* Wq = (const float*)d_in[1];
    const float* Wk = (const float*)d_in[2];
    float* out = (float*)d_out;

    cudaFuncSetAttribute(proj_tc, cudaFuncAttributeMaxDynamicSharedMemorySize, 32768);
    cudaFuncSetAttribute(attn_tc, cudaFuncAttributeMaxDynamicSharedMemorySize, 40960);

    round_inputs<<<1184, 256>>>(g, Wq, Wk);
    proj_tc<<<dim3(12, 32, 2), 128, 32768>>>();
    attn_tc<<<dim3(32, H_HEADS), 256, 40960>>>(out);
}

// round 10
// speedup vs baseline: 1.1416x; 1.0930x over previous
#include <cuda_runtime.h>
#include <cuda_bf16.h>
#include <cstdint>
#include <math.h>

#define N_TOK 2048
#define D_DIM 768
#define HY 768
#define H_HEADS 12

// Scratch (allocation-free rule: device globals)
__device__ __nv_bfloat16 g_gr[N_TOK * D_DIM];   // bf16-rounded g
__device__ __nv_bfloat16 g_wqr[HY * D_DIM];     // bf16-rounded Wq
__device__ __nv_bfloat16 g_wkr[HY * D_DIM];     // bf16-rounded Wk
__device__ __nv_bfloat16 g_Q[N_TOK * HY];       // bf16, scaled by beta*log2e
__device__ __nv_bfloat16 g_K[N_TOK * HY];       // bf16
__device__ float g_partial[H_HEADS * 32];       // 384 per-block LSE2 sums
__device__ int   g_count;                       // last-block counter (self-resetting)

// ---------------------------------------------------------------------------
__device__ __forceinline__ uint32_t smem_u32(const void* p) {
    uint32_t a;
    asm("{ .reg .u64 t; cvta.to.shared.u64 t, %1; cvt.u32.u64 %0, t; }"
        : "=r"(a) : "l"(p));
    return a;
}
__device__ __forceinline__ uint32_t pack_bf2(float x, float y) {
    __nv_bfloat162 h = __floats2bfloat162_rn(x, y);
    return *reinterpret_cast<uint32_t*>(&h);
}
__device__ __forceinline__ void ldmx4(uint32_t r[4], uint32_t addr) {
    asm volatile("ldmatrix.sync.aligned.m8n8.x4.shared.b16 {%0,%1,%2,%3}, [%4];"
                 : "=r"(r[0]), "=r"(r[1]), "=r"(r[2]), "=r"(r[3]) : "r"(addr));
}
__device__ __forceinline__ void mma_bf16(float c[4], const uint32_t a[4],
                                         uint32_t b0, uint32_t b1) {
    asm volatile(
        "mma.sync.aligned.m16n8k16.row.col.f32.bf16.bf16.f32 "
        "{%0,%1,%2,%3}, {%4,%5,%6,%7}, {%8,%9}, {%0,%1,%2,%3};"
        : "+f"(c[0]), "+f"(c[1]), "+f"(c[2]), "+f"(c[3])
        : "r"(a[0]), "r"(a[1]), "r"(a[2]), "r"(a[3]), "r"(b0), "r"(b1));
}
#define CP_ASYNC16(dst, src) \
    asm volatile("cp.async.cg.shared.global [%0], [%1], 16;" :: "r"(dst), "l"(src))
#define CP_COMMIT() asm volatile("cp.async.commit_group;" ::: "memory")
#define CP_WAIT1()  asm volatile("cp.async.wait_group 1;" ::: "memory")

// ---------------------------------------------------------------------------
// Pre-round all inputs to bf16.
// ---------------------------------------------------------------------------
__global__ __launch_bounds__(256) void round_inputs(const float* __restrict__ g,
                                                    const float* __restrict__ wq,
                                                    const float* __restrict__ wk) {
    const int stride = gridDim.x * blockDim.x;
    const int i0 = blockIdx.x * blockDim.x + threadIdx.x;
    const int NG = N_TOK * D_DIM / 4, NW = HY * D_DIM / 4;
    const float4* g4  = (const float4*)g;
    const float4* wq4 = (const float4*)wq;
    const float4* wk4 = (const float4*)wk;
    uint2* og = (uint2*)g_gr;
    uint2* oq = (uint2*)g_wqr;
    uint2* ok = (uint2*)g_wkr;
    for (int t = i0; t < NG; t += stride) {
        float4 v = g4[t];
        og[t] = make_uint2(pack_bf2(v.x, v.y), pack_bf2(v.z, v.w));
    }
    for (int t = i0; t < NW; t += stride) {
        float4 v = wq4[t];
        oq[t] = make_uint2(pack_bf2(v.x, v.y), pack_bf2(v.z, v.w));
        float4 w = wk4[t];
        ok[t] = make_uint2(pack_bf2(w.x, w.y), pack_bf2(w.z, w.w));
    }
}

// ---------------------------------------------------------------------------
// Projection: Out[n][j] = sum_d G[n][d]*W[j][d].  z=0: Wq->g_Q (*beta*log2e).
// Tile 128x64, k-stage 64 bf16, 12 stages, 128 threads (2x2 warps, warp 64x32),
// cp.async 2-stage pipeline.  (Identical to the 57.9us R7 version.)
// Dynamic smem 48KB: As[2] @0/16K (16KB each), Bs[2] @32K/40K (8KB each).
// ---------------------------------------------------------------------------
__global__ __launch_bounds__(128) void proj_tc() {
    extern __shared__ uint32_t smd[];
    const uint32_t sb = smem_u32(smd);

    const int z = blockIdx.z;
    const __nv_bfloat16* __restrict__ W = z ? g_wkr : g_wqr;
    __nv_bfloat16* __restrict__ Out = z ? g_K : g_Q;
    const float scale = z ? 1.0f : 0.18033688011112042f;  // beta*log2(e)

    const int bm = blockIdx.y * 128, bn = blockIdx.x * 64;
    const int tid = threadIdx.x, lane = tid & 31, wid = tid >> 5;
    const int wm = wid >> 1, wn = wid & 1;
    const int lrow = tid >> 3, lg = tid & 7;   // loader: 16 rows x 8 granules(16B)

    auto issue = [&](int s, int buf) {
        const int kt = s * 64;
        const uint32_t Ab = sb + buf * 16384;
        const uint32_t Bb = sb + 32768 + buf * 8192;
#pragma unroll
        for (int i = 0; i < 8; i++) {
            int row = i * 16 + lrow;
            CP_ASYNC16(Ab + (uint32_t)(row * 8 + (lg ^ (row & 7))) * 16,
                       &g_gr[(size_t)(bm + row) * D_DIM + kt + lg * 8]);
        }
#pragma unroll
        for (int i = 0; i < 4; i++) {
            int row = i * 16 + lrow;
            CP_ASYNC16(Bb + (uint32_t)(row * 8 + (lg ^ (row & 7))) * 16,
                       &W[(size_t)(bn + row) * D_DIM + kt + lg * 8]);
        }
    };

    issue(0, 0); CP_COMMIT();
    issue(1, 1); CP_COMMIT();

    float c[4][4][4];
#pragma unroll
    for (int mf = 0; mf < 4; mf++)
#pragma unroll
        for (int nf = 0; nf < 4; nf++)
#pragma unroll
            for (int q = 0; q < 4; q++) c[mf][nf][q] = 0.f;

    const int mlo = (lane >> 3) & 1, mhi = lane >> 4, r8 = lane & 7;

    for (int s = 0; s < 12; s++) {
        CP_WAIT1();
        __syncthreads();
        const int buf = s & 1;
        const uint32_t Ab = sb + buf * 16384;
        const uint32_t Bb = sb + 32768 + buf * 8192;
#pragma unroll
        for (int ks = 0; ks < 4; ks++) {
            uint32_t a[4][4];
#pragma unroll
            for (int mf = 0; mf < 4; mf++) {
                int row = wm * 64 + mf * 16 + mlo * 8 + r8;
                int g = 2 * ks + mhi;
                ldmx4(a[mf], Ab + (uint32_t)(row * 8 + (g ^ (row & 7))) * 16);
            }
#pragma unroll
            for (int p = 0; p < 2; p++) {
                uint32_t b[4];
                int row = wn * 32 + p * 16 + mhi * 8 + r8;
                int g = 2 * ks + mlo;
                ldmx4(b, Bb + (uint32_t)(row * 8 + (g ^ (row & 7))) * 16);
#pragma unroll
                for (int mf = 0; mf < 4; mf++) {
                    mma_bf16(c[mf][2 * p],     a[mf], b[0], b[1]);
                    mma_bf16(c[mf][2 * p + 1], a[mf], b[2], b[3]);
                }
            }
        }
        __syncthreads();
        if (s + 2 < 12) issue(s + 2, buf);
        CP_COMMIT();
    }

    // store C as bf16 (attn consumes without conversion)
#pragma unroll
    for (int mf = 0; mf < 4; mf++) {
        int row = bm + wm * 64 + mf * 16 + (lane >> 2);
#pragma unroll
        for (int nf = 0; nf < 4; nf++) {
            int col = bn + wn * 32 + nf * 8 + 2 * (lane & 3);
            *(uint32_t*)&Out[(size_t)row * HY + col] =
                pack_bf2(c[mf][nf][0] * scale, c[mf][nf][1] * scale);
            *(uint32_t*)&Out[(size_t)(row + 8) * HY + col] =
                pack_bf2(c[mf][nf][2] * scale, c[mf][nf][3] * scale);
        }
    }
}

// ---------------------------------------------------------------------------
// Attention LSE: block = (64 q rows, head). 4 warps; warp w owns rows w*16..+15.
// K tiles of 128 rows (16KB bf16), cp.async 2-stage. Online log2-domain softmax
// with PER-LANE independent (m,s) — no shuffles in the main loop; per-lane
// tile-skip (>40 log2-units below that lane's max). Exact 4-lane merge at end.
// Last block performs the final 384-partial reduction and resets the counter.
// Dynamic smem 40KB: Qs @0 (8KB), Ks[2] @8K/24K (16KB each).
// ---------------------------------------------------------------------------
__global__ __launch_bounds__(128) void attn_tc(float* __restrict__ out) {
    extern __shared__ uint32_t smd[];
    const uint32_t sb = smem_u32(smd);
    __shared__ float red[64];
    __shared__ int last;

    const int h = blockIdx.y, qb = blockIdx.x, q0 = qb * 64;
    const int tid = threadIdx.x, lane = tid & 31, wid = tid >> 5;
    const int lrow = tid >> 3, lg = tid & 7;   // loader: 16 rows x 8 granules

    // issue Q (64 rows)
#pragma unroll
    for (int i = 0; i < 4; i++) {
        int row = i * 16 + lrow;
        CP_ASYNC16(sb + (uint32_t)(row * 8 + (lg ^ (row & 7))) * 16,
                   &g_Q[(size_t)(q0 + row) * HY + h * 64 + lg * 8]);
    }
    CP_COMMIT();

    auto issueK = [&](int t, int buf) {
        const uint32_t Kb = sb + 8192 + buf * 16384;
#pragma unroll
        for (int i = 0; i < 8; i++) {
            int row = i * 16 + lrow;
            CP_ASYNC16(Kb + (uint32_t)(row * 8 + (lg ^ (row & 7))) * 16,
                       &g_K[(size_t)(t * 128 + row) * HY + h * 64 + lg * 8]);
        }
    };
    issueK(0, 0); CP_COMMIT();
    issueK(1, 1); CP_COMMIT();

    CP_WAIT1();          // Q + K0 complete
    __syncthreads();

    // preload Q fragments (4 ksteps x 4 regs)
    const int mlo = (lane >> 3) & 1, mhi = lane >> 4, r8 = lane & 7;
    uint32_t QA[4][4];
#pragma unroll
    for (int ks = 0; ks < 4; ks++) {
        int row = wid * 16 + mlo * 8 + r8;
        int g = 2 * ks + mhi;
        ldmx4(QA[ks], sb + (uint32_t)(row * 8 + (g ^ (row & 7))) * 16);
    }

    // per-lane independent online state (row r: m0/s0, row r+8: m1/s1)
    float m0 = -1e30f, m1 = -1e30f, s0 = 0.f, s1 = 0.f;

    for (int t = 0; t < 16; t++) {
        if (t > 0) { CP_WAIT1(); __syncthreads(); }
        const uint32_t Kb = sb + 8192 + (t & 1) * 16384;

        float c[16][4];
#pragma unroll
        for (int nf = 0; nf < 16; nf++)
#pragma unroll
            for (int q = 0; q < 4; q++) c[nf][q] = 0.f;

#pragma unroll
        for (int ks = 0; ks < 4; ks++) {
#pragma unroll
            for (int p = 0; p < 8; p++) {
                uint32_t b[4];
                int row = p * 16 + mhi * 8 + r8;
                int g = 2 * ks + mlo;
                ldmx4(b, Kb + (uint32_t)(row * 8 + (g ^ (row & 7))) * 16);
                mma_bf16(c[2 * p],     QA[ks], b[0], b[1]);
                mma_bf16(c[2 * p + 1], QA[ks], b[2], b[3]);
            }
        }
        __syncthreads();
        if (t + 2 < 16) issueK(t + 2, t & 1);
        CP_COMMIT();

        // per-lane tile max over this lane's 32 columns (no shuffles)
        float lm0 = -1e30f, lm1 = -1e30f;
#pragma unroll
        for (int nf = 0; nf < 16; nf++) {
            lm0 = fmaxf(lm0, fmaxf(c[nf][0], c[nf][1]));
            lm1 = fmaxf(lm1, fmaxf(c[nf][2], c[nf][3]));
        }

        // per-lane skip: dropped mass <= 32 * 2^(m-40), negligible vs s
        if (lm0 >= m0 - 40.f) {
            float mn = fmaxf(m0, lm0);
            float p = 0.f;
#pragma unroll
            for (int nf = 0; nf < 16; nf++)
                p += exp2f(c[nf][0] - mn) + exp2f(c[nf][1] - mn);
            s0 = s0 * exp2f(m0 - mn) + p;
            m0 = mn;
        }
        if (lm1 >= m1 - 40.f) {
            float mn = fmaxf(m1, lm1);
            float p = 0.f;
#pragma unroll
            for (int nf = 0; nf < 16; nf++)
                p += exp2f(c[nf][2] - mn) + exp2f(c[nf][3] - mn);
            s1 = s1 * exp2f(m1 - mn) + p;
            m1 = mn;
        }
    }

    // exact 4-lane merge of per-lane (m,s): mm = max m_l; s = sum s_l*2^(m_l-mm)
    float mm0 = m0, mm1 = m1;
    mm0 = fmaxf(mm0, __shfl_xor_sync(0xffffffffu, mm0, 1));
    mm0 = fmaxf(mm0, __shfl_xor_sync(0xffffffffu, mm0, 2));
    mm1 = fmaxf(mm1, __shfl_xor_sync(0xffffffffu, mm1, 1));
    mm1 = fmaxf(mm1, __shfl_xor_sync(0xffffffffu, mm1, 2));
    float t0 = s0 * exp2f(m0 - mm0);
    float t1 = s1 * exp2f(m1 - mm1);
    t0 += __shfl_xor_sync(0xffffffffu, t0, 1);
    t0 += __shfl_xor_sync(0xffffffffu, t0, 2);
    t1 += __shfl_xor_sync(0xffffffffu, t1, 1);
    t1 += __shfl_xor_sync(0xffffffffu, t1, 2);

    if ((lane & 3) == 0) {
        red[wid * 16 + (lane >> 2)]     = mm0 + log2f(t0);
        red[wid * 16 + (lane >> 2) + 8] = mm1 + log2f(t1);
    }
    __syncthreads();
    if (tid < 32) {
        float v = red[tid] + red[tid + 32];
#pragma unroll
        for (int off = 16; off > 0; off >>= 1)
            v += __shfl_xor_sync(0xffffffffu, v, off);
        if (tid == 0) g_partial[h * 32 + qb] = v;
    }

    // --- fused final reduction: last arriving block sums all 384 partials ---
    if (tid == 0) {
        __threadfence();
        last = (atomicAdd(&g_count, 1) == H_HEADS * 32 - 1);
    }
    __syncthreads();
    if (last) {
        __threadfence();
        float v = g_partial[tid] + g_partial[tid + 128] + g_partial[tid + 256];
#pragma unroll
        for (int off = 16; off > 0; off >>= 1)
            v += __shfl_xor_sync(0xffffffffu, v, off);
        if (lane == 0) red[wid] = v;
        __syncthreads();
        if (tid == 0) {
            out[0] = -5.545177444479562f * (red[0] + red[1] + red[2] + red[3]);
            g_count = 0;   // reset for next graph replay
        }
    }
}

// ---------------------------------------------------------------------------
extern "C" void kernel_launch(void* const* d_in, const int* in_sizes, int n_in,
                              void* d_out, int out_size) {
    const float* g  = (const float*)d_in[0];
    const float* Wq = (const float*)d_in[1];
    const float* Wk = (const float*)d_in[2];
    float* out = (float*)d_out;

    cudaFuncSetAttribute(proj_tc, cudaFuncAttributeMaxDynamicSharedMemorySize, 49152);
    cudaFuncSetAttribute(attn_tc, cudaFuncAttributeMaxDynamicSharedMemorySize, 40960);

    round_inputs<<<1184, 256>>>(g, Wq, Wk);
    proj_tc<<<dim3(12, 16, 2), 128, 49152>>>();
    attn_tc<<<dim3(32, H_HEADS), 128, 40960>>>(out);
}

// round 13
// speedup vs baseline: 1.1514x; 1.0086x over previous
#include <cuda_runtime.h>
#include <cuda_bf16.h>
#include <cstdint>
#include <math.h>

#define N_TOK 2048
#define D_DIM 768
#define HY 768
#define H_HEADS 12

// Scratch (allocation-free rule: device globals)
__device__ __nv_bfloat16 g_gr[N_TOK * D_DIM];   // bf16-rounded g
__device__ __nv_bfloat16 g_wqr[HY * D_DIM];     // bf16-rounded Wq
__device__ __nv_bfloat16 g_wkr[HY * D_DIM];     // bf16-rounded Wk
__device__ __nv_bfloat16 g_Q[N_TOK * HY];       // bf16, scaled by beta*log2e
__device__ __nv_bfloat16 g_K[N_TOK * HY];       // bf16
__device__ float g_partial[H_HEADS * 32];       // 384 per-block LSE2 sums
__device__ int   g_count;                       // last-block counter (self-resetting)

// ---------------------------------------------------------------------------
__device__ __forceinline__ uint32_t smem_u32(const void* p) {
    uint32_t a;
    asm("{ .reg .u64 t; cvta.to.shared.u64 t, %1; cvt.u32.u64 %0, t; }"
        : "=r"(a) : "l"(p));
    return a;
}
__device__ __forceinline__ uint32_t pack_bf2(float x, float y) {
    __nv_bfloat162 h = __floats2bfloat162_rn(x, y);
    return *reinterpret_cast<uint32_t*>(&h);
}
__device__ __forceinline__ float ex2(float x) {   // raw MUFU.EX2
    float r;
    asm("ex2.approx.ftz.f32 %0, %1;" : "=f"(r) : "f"(x));
    return r;
}
__device__ __forceinline__ float lg2(float x) {   // raw MUFU.LG2
    float r;
    asm("lg2.approx.f32 %0, %1;" : "=f"(r) : "f"(x));
    return r;
}
__device__ __forceinline__ void ldmx4(uint32_t r[4], uint32_t addr) {
    asm volatile("ldmatrix.sync.aligned.m8n8.x4.shared.b16 {%0,%1,%2,%3}, [%4];"
                 : "=r"(r[0]), "=r"(r[1]), "=r"(r[2]), "=r"(r[3]) : "r"(addr));
}
__device__ __forceinline__ void mma_bf16(float c[4], const uint32_t a[4],
                                         uint32_t b0, uint32_t b1) {
    asm volatile(
        "mma.sync.aligned.m16n8k16.row.col.f32.bf16.bf16.f32 "
        "{%0,%1,%2,%3}, {%4,%5,%6,%7}, {%8,%9}, {%0,%1,%2,%3};"
        : "+f"(c[0]), "+f"(c[1]), "+f"(c[2]), "+f"(c[3])
        : "r"(a[0]), "r"(a[1]), "r"(a[2]), "r"(a[3]), "r"(b0), "r"(b1));
}
#define CP_ASYNC16(dst, src) \
    asm volatile("cp.async.cg.shared.global [%0], [%1], 16;" :: "r"(dst), "l"(src))
#define CP_COMMIT() asm volatile("cp.async.commit_group;" ::: "memory")
#define CP_WAIT1()  asm volatile("cp.async.wait_group 1;" ::: "memory")

// ---------------------------------------------------------------------------
// Pre-round all inputs to bf16.  Flat uint4 index space over {g, Wq, Wk};
// each thread converts 4 float4s with all 4 loads in flight (MLP=4).
// Totals: NG4=393216, NW4=147456 each; grand total 688128 float4s.
// Grid 672 x 256 = 172032 threads x 4 = 688128.  (exact cover)
// ---------------------------------------------------------------------------
__global__ __launch_bounds__(256) void round_inputs(const float* __restrict__ g,
                                                    const float* __restrict__ wq,
                                                    const float* __restrict__ wk) {
    const int NG4 = N_TOK * D_DIM / 4;   // 393216
    const int NW4 = HY * D_DIM / 4;      // 147456
    const int base = (blockIdx.x * blockDim.x + threadIdx.x) * 4;

    float4 v[4];
    const float4* src[4];
    uint32_t dsti[4];
#pragma unroll
    for (int j = 0; j < 4; j++) {
        int idx = base + j;
        const float4* s;
        uint2* d;
        if (idx < NG4)            { s = (const float4*)g  + idx;
                                    d = (uint2*)g_gr  + idx; }
        else if (idx < NG4 + NW4) { s = (const float4*)wq + (idx - NG4);
                                    d = (uint2*)g_wqr + (idx - NG4); }
        else                      { s = (const float4*)wk + (idx - NG4 - NW4);
                                    d = (uint2*)g_wkr + (idx - NG4 - NW4); }
        src[j] = s;
        dsti[j] = (uint32_t)(uintptr_t)d;   // stash; recompute below
    }
    // issue all 4 loads back-to-back (independent)
#pragma unroll
    for (int j = 0; j < 4; j++) v[j] = *src[j];
    // convert + store
#pragma unroll
    for (int j = 0; j < 4; j++) {
        int idx = base + j;
        uint2* d;
        if (idx < NG4)            d = (uint2*)g_gr  + idx;
        else if (idx < NG4 + NW4) d = (uint2*)g_wqr + (idx - NG4);
        else                      d = (uint2*)g_wkr + (idx - NG4 - NW4);
        (void)dsti;
        *d = make_uint2(pack_bf2(v[j].x, v[j].y), pack_bf2(v[j].z, v[j].w));
    }
}

// ---------------------------------------------------------------------------
// Projection: Out[n][j] = sum_d G[n][d]*W[j][d].  z=0: Wq->g_Q (*beta*log2e).
// Tile 128x64, k-stage 64 bf16, 12 stages, 128 threads (2x2 warps, warp 64x32),
// cp.async 2-stage pipeline.  (Identical to the 56.1us R10 version.)
// Dynamic smem 48KB: As[2] @0/16K (16KB each), Bs[2] @32K/40K (8KB each).
// ---------------------------------------------------------------------------
__global__ __launch_bounds__(128) void proj_tc() {
    extern __shared__ uint32_t smd[];
    const uint32_t sb = smem_u32(smd);

    const int z = blockIdx.z;
    const __nv_bfloat16* __restrict__ W = z ? g_wkr : g_wqr;
    __nv_bfloat16* __restrict__ Out = z ? g_K : g_Q;
    const float scale = z ? 1.0f : 0.18033688011112042f;  // beta*log2(e)

    const int bm = blockIdx.y * 128, bn = blockIdx.x * 64;
    const int tid = threadIdx.x, lane = tid & 31, wid = tid >> 5;
    const int wm = wid >> 1, wn = wid & 1;
    const int lrow = tid >> 3, lg = tid & 7;   // loader: 16 rows x 8 granules(16B)

    auto issue = [&](int s, int buf) {
        const int kt = s * 64;
        const uint32_t Ab = sb + buf * 16384;
        const uint32_t Bb = sb + 32768 + buf * 8192;
#pragma unroll
        for (int i = 0; i < 8; i++) {
            int row = i * 16 + lrow;
            CP_ASYNC16(Ab + (uint32_t)(row * 8 + (lg ^ (row & 7))) * 16,
                       &g_gr[(size_t)(bm + row) * D_DIM + kt + lg * 8]);
        }
#pragma unroll
        for (int i = 0; i < 4; i++) {
            int row = i * 16 + lrow;
            CP_ASYNC16(Bb + (uint32_t)(row * 8 + (lg ^ (row & 7))) * 16,
                       &W[(size_t)(bn + row) * D_DIM + kt + lg * 8]);
        }
    };

    issue(0, 0); CP_COMMIT();
    issue(1, 1); CP_COMMIT();

    float c[4][4][4];
#pragma unroll
    for (int mf = 0; mf < 4; mf++)
#pragma unroll
        for (int nf = 0; nf < 4; nf++)
#pragma unroll
            for (int q = 0; q < 4; q++) c[mf][nf][q] = 0.f;

    const int mlo = (lane >> 3) & 1, mhi = lane >> 4, r8 = lane & 7;

    for (int s = 0; s < 12; s++) {
        CP_WAIT1();
        __syncthreads();
        const int buf = s & 1;
        const uint32_t Ab = sb + buf * 16384;
        const uint32_t Bb = sb + 32768 + buf * 8192;
#pragma unroll
        for (int ks = 0; ks < 4; ks++) {
            uint32_t a[4][4];
#pragma unroll
            for (int mf = 0; mf < 4; mf++) {
                int row = wm * 64 + mf * 16 + mlo * 8 + r8;
                int g = 2 * ks + mhi;
                ldmx4(a[mf], Ab + (uint32_t)(row * 8 + (g ^ (row & 7))) * 16);
            }
#pragma unroll
            for (int p = 0; p < 2; p++) {
                uint32_t b[4];
                int row = wn * 32 + p * 16 + mhi * 8 + r8;
                int g = 2 * ks + mlo;
                ldmx4(b, Bb + (uint32_t)(row * 8 + (g ^ (row & 7))) * 16);
#pragma unroll
                for (int mf = 0; mf < 4; mf++) {
                    mma_bf16(c[mf][2 * p],     a[mf], b[0], b[1]);
                    mma_bf16(c[mf][2 * p + 1], a[mf], b[2], b[3]);
                }
            }
        }
        __syncthreads();
        if (s + 2 < 12) issue(s + 2, buf);
        CP_COMMIT();
    }

    // store C as bf16 (attn consumes without conversion)
#pragma unroll
    for (int mf = 0; mf < 4; mf++) {
        int row = bm + wm * 64 + mf * 16 + (lane >> 2);
#pragma unroll
        for (int nf = 0; nf < 4; nf++) {
            int col = bn + wn * 32 + nf * 8 + 2 * (lane & 3);
            *(uint32_t*)&Out[(size_t)row * HY + col] =
                pack_bf2(c[mf][nf][0] * scale, c[mf][nf][1] * scale);
            *(uint32_t*)&Out[(size_t)(row + 8) * HY + col] =
                pack_bf2(c[mf][nf][2] * scale, c[mf][nf][3] * scale);
        }
    }
}

// ---------------------------------------------------------------------------
// Attention LSE: block = (64 q rows, head). 4 warps; warp w owns rows w*16..+15.
// K tiles of 128 rows (16KB bf16), cp.async 2-stage. Online log2-domain softmax
// with PER-LANE independent (m,s) — no shuffles in the main loop; per-lane
// tile-skip (>40 log2-units below that lane's max). Exact 4-lane merge at end.
// Raw MUFU ex2/lg2 (error ~2^-21, negligible vs bf16 score noise).
// Last block performs the final 384-partial reduction and resets the counter.
// Dynamic smem 40KB: Qs @0 (8KB), Ks[2] @8K/24K (16KB each).
// ---------------------------------------------------------------------------
__global__ __launch_bounds__(128) void attn_tc(float* __restrict__ out) {
    extern __shared__ uint32_t smd[];
    const uint32_t sb = smem_u32(smd);
    __shared__ float red[64];
    __shared__ int last;

    const int h = blockIdx.y, qb = blockIdx.x, q0 = qb * 64;
    const int tid = threadIdx.x, lane = tid & 31, wid = tid >> 5;
    const int lrow = tid >> 3, lg = tid & 7;   // loader: 16 rows x 8 granules

    // issue Q (64 rows)
#pragma unroll
    for (int i = 0; i < 4; i++) {
        int row = i * 16 + lrow;
        CP_ASYNC16(sb + (uint32_t)(row * 8 + (lg ^ (row & 7))) * 16,
                   &g_Q[(size_t)(q0 + row) * HY + h * 64 + lg * 8]);
    }
    CP_COMMIT();

    auto issueK = [&](int t, int buf) {
        const uint32_t Kb = sb + 8192 + buf * 16384;
#pragma unroll
        for (int i = 0; i < 8; i++) {
            int row = i * 16 + lrow;
            CP_ASYNC16(Kb + (uint32_t)(row * 8 + (lg ^ (row & 7))) * 16,
                       &g_K[(size_t)(t * 128 + row) * HY + h * 64 + lg * 8]);
        }
    };
    issueK(0, 0); CP_COMMIT();
    issueK(1, 1); CP_COMMIT();

    CP_WAIT1();          // Q + K0 complete
    __syncthreads();

    // preload Q fragments (4 ksteps x 4 regs)
    const int mlo = (lane >> 3) & 1, mhi = lane >> 4, r8 = lane & 7;
    uint32_t QA[4][4];
#pragma unroll
    for (int ks = 0; ks < 4; ks++) {
        int row = wid * 16 + mlo * 8 + r8;
        int g = 2 * ks + mhi;
        ldmx4(QA[ks], sb + (uint32_t)(row * 8 + (g ^ (row & 7))) * 16);
    }

    // per-lane independent online state (row r: m0/s0, row r+8: m1/s1)
    float m0 = -1e30f, m1 = -1e30f, s0 = 0.f, s1 = 0.f;

    for (int t = 0; t < 16; t++) {
        if (t > 0) { CP_WAIT1(); __syncthreads(); }
        const uint32_t Kb = sb + 8192 + (t & 1) * 16384;

        float c[16][4];
#pragma unroll
        for (int nf = 0; nf < 16; nf++)
#pragma unroll
            for (int q = 0; q < 4; q++) c[nf][q] = 0.f;

#pragma unroll
        for (int ks = 0; ks < 4; ks++) {
#pragma unroll
            for (int p = 0; p < 8; p++) {
                uint32_t b[4];
                int row = p * 16 + mhi * 8 + r8;
                int g = 2 * ks + mlo;
                ldmx4(b, Kb + (uint32_t)(row * 8 + (g ^ (row & 7))) * 16);
                mma_bf16(c[2 * p],     QA[ks], b[0], b[1]);
                mma_bf16(c[2 * p + 1], QA[ks], b[2], b[3]);
            }
        }
        __syncthreads();
        if (t + 2 < 16) issueK(t + 2, t & 1);
        CP_COMMIT();

        // per-lane tile max over this lane's 32 columns (no shuffles)
        float lm0 = -1e30f, lm1 = -1e30f;
#pragma unroll
        for (int nf = 0; nf < 16; nf++) {
            lm0 = fmaxf(lm0, fmaxf(c[nf][0], c[nf][1]));
            lm1 = fmaxf(lm1, fmaxf(c[nf][2], c[nf][3]));
        }

        // per-lane skip: dropped mass <= 32 * 2^(m-40), negligible vs s
        if (lm0 >= m0 - 40.f) {
            float mn = fmaxf(m0, lm0);
            float p = 0.f;
#pragma unroll
            for (int nf = 0; nf < 16; nf++)
                p += ex2(c[nf][0] - mn) + ex2(c[nf][1] - mn);
            s0 = s0 * ex2(m0 - mn) + p;
            m0 = mn;
        }
        if (lm1 >= m1 - 40.f) {
            float mn = fmaxf(m1, lm1);
            float p = 0.f;
#pragma unroll
            for (int nf = 0; nf < 16; nf++)
                p += ex2(c[nf][2] - mn) + ex2(c[nf][3] - mn);
            s1 = s1 * ex2(m1 - mn) + p;
            m1 = mn;
        }
    }

    // exact 4-lane merge of per-lane (m,s): mm = max m_l; s = sum s_l*2^(m_l-mm)
    float mm0 = m0, mm1 = m1;
    mm0 = fmaxf(mm0, __shfl_xor_sync(0xffffffffu, mm0, 1));
    mm0 = fmaxf(mm0, __shfl_xor_sync(0xffffffffu, mm0, 2));
    mm1 = fmaxf(mm1, __shfl_xor_sync(0xffffffffu, mm1, 1));
    mm1 = fmaxf(mm1, __shfl_xor_sync(0xffffffffu, mm1, 2));
    float t0 = s0 * ex2(m0 - mm0);
    float t1 = s1 * ex2(m1 - mm1);
    t0 += __shfl_xor_sync(0xffffffffu, t0, 1);
    t0 += __shfl_xor_sync(0xffffffffu, t0, 2);
    t1 += __shfl_xor_sync(0xffffffffu, t1, 1);
    t1 += __shfl_xor_sync(0xffffffffu, t1, 2);

    if ((lane & 3) == 0) {
        red[wid * 16 + (lane >> 2)]     = mm0 + lg2(t0);
        red[wid * 16 + (lane >> 2) + 8] = mm1 + lg2(t1);
    }
    __syncthreads();
    if (tid < 32) {
        float v = red[tid] + red[tid + 32];
#pragma unroll
        for (int off = 16; off > 0; off >>= 1)
            v += __shfl_xor_sync(0xffffffffu, v, off);
        if (tid == 0) g_partial[h * 32 + qb] = v;
    }

    // --- fused final reduction: last arriving block sums all 384 partials ---
    if (tid == 0) {
        __threadfence();
        last = (atomicAdd(&g_count, 1) == H_HEADS * 32 - 1);
    }
    __syncthreads();
    if (last) {
        __threadfence();
        float v = g_partial[tid] + g_partial[tid + 128] + g_partial[tid + 256];
#pragma unroll
        for (int off = 16; off > 0; off >>= 1)
            v += __shfl_xor_sync(0xffffffffu, v, off);
        if (lane == 0) red[wid] = v;
        __syncthreads();
        if (tid == 0) {
            out[0] = -5.545177444479562f * (red[0] + red[1] + red[2] + red[3]);
            g_count = 0;   // reset for next graph replay
        }
    }
}

// ---------------------------------------------------------------------------
extern "C" void kernel_launch(void* const* d_in, const int* in_sizes, int n_in,
                              void* d_out, int out_size) {
    const float* g  = (const float*)d_in[0];
    const float* Wq = (const float*)d_in[1];
    const float* Wk = (const float*)d_in[2];
    float* out = (float*)d_out;

    cudaFuncSetAttribute(proj_tc, cudaFuncAttributeMaxDynamicSharedMemorySize, 49152);
    cudaFuncSetAttribute(attn_tc, cudaFuncAttributeMaxDynamicSharedMemorySize, 40960);

    round_inputs<<<672, 256>>>(g, Wq, Wk);
    proj_tc<<<dim3(12, 16, 2), 128, 49152>>>();
    attn_tc<<<dim3(32, H_HEADS), 128, 40960>>>(out);
}